// round 2
// baseline (speedup 1.0000x reference)
#include <cuda_runtime.h>
#include <math.h>

#define H  256
#define B  512
#define T  256
#define BT (B*T)

// ---------------- device scratch (no allocations allowed) ----------------
__device__ float gM[H * H];        // M = W_oI @ W_Ih
__device__ float gGT[H];           // W_oI @ W_I1T
__device__ float gGL[H];           // W_oI @ W_I1L
__device__ float gU[B * H];        // u_b = W_oI @ (cp_b + b_I) + b_oI
__device__ float gScores[BT];      // pre-softmax scores

// ---------------- packed f32x2 helpers (sm_103a FFMA2 path) ----------------
__device__ __forceinline__ unsigned long long pack2(float a, float b) {
    unsigned long long r;
    asm("mov.b64 %0, {%1, %2};" : "=l"(r) : "f"(a), "f"(b));
    return r;
}
__device__ __forceinline__ float2 unpack2(unsigned long long v) {
    float2 f;
    asm("mov.b64 {%0, %1}, %2;" : "=f"(f.x), "=f"(f.y) : "l"(v));
    return f;
}
__device__ __forceinline__ void ffma2(unsigned long long& d,
                                      unsigned long long a,
                                      unsigned long long b) {
    asm("fma.rn.f32x2 %0, %1, %2, %0;" : "+l"(d) : "l"(a), "l"(b));
}

// ---------------- k_vec: gT = W_oI@wT, gL = W_oI@wL (1 block) ----------------
__global__ void k_vec(const float* __restrict__ W_oI,
                      const float* __restrict__ wT,
                      const float* __restrict__ wL) {
    int o = threadIdx.x;
    float at = 0.f, al = 0.f;
    const float* wr = W_oI + o * H;
    for (int i = 0; i < H; i++) {
        float w = wr[i];
        at += w * wT[i];
        al += w * wL[i];
    }
    gGT[o] = at;
    gGL[o] = al;
}

// ---------------- k_M: M = W_oI @ W_Ih  (64 blocks x 256 thr, 4 rows/blk) ---
__global__ void k_M(const float* __restrict__ W_oI,
                    const float* __restrict__ W_Ih) {
    __shared__ float sWo[4][H];
    int h  = threadIdx.x;
    int o0 = blockIdx.x * 4;
    #pragma unroll
    for (int r = 0; r < 4; r++) sWo[r][h] = W_oI[(o0 + r) * H + h];
    __syncthreads();
    float a0 = 0.f, a1 = 0.f, a2 = 0.f, a3 = 0.f;
    for (int i = 0; i < H; i++) {
        float w = W_Ih[i * H + h];          // coalesced across threads
        a0 += sWo[0][i] * w;                // smem broadcast
        a1 += sWo[1][i] * w;
        a2 += sWo[2][i] * w;
        a3 += sWo[3][i] * w;
    }
    gM[(o0 + 0) * H + h] = a0;
    gM[(o0 + 1) * H + h] = a1;
    gM[(o0 + 2) * H + h] = a2;
    gM[(o0 + 3) * H + h] = a3;
}

// ---------------- k_u: u_b for 8 batches per block (64 blocks) --------------
__global__ void k_u(const float* __restrict__ h_tilde,
                    const float* __restrict__ c_t,
                    const float* __restrict__ W_I,
                    const float* __restrict__ W_oI,
                    const float* __restrict__ b_I,
                    const float* __restrict__ b_oI) {
    __shared__ float hh[8][2 * H];   // h_hat rows, 16 KB
    __shared__ float cps[8][H];      // cp + b_I,   8 KB
    int tid = threadIdx.x;
    int b0  = blockIdx.x * 8;

    for (int idx = tid; idx < 8 * 2 * H; idx += 256) {
        int bb = idx >> 9, j = idx & (2 * H - 1);
        hh[bb][j] = (j < H) ? h_tilde[(b0 + bb) * H + j]
                            : c_t[(b0 + bb) * H + (j - H)];
    }
    __syncthreads();

    {   // cp[b,i] = h_hat_b . W_I[i,:]   (i = tid)
        float acc[8];
        #pragma unroll
        for (int bb = 0; bb < 8; bb++) acc[bb] = 0.f;
        const float* wr = W_I + tid * 2 * H;
        for (int j = 0; j < 2 * H; j++) {
            float w = wr[j];
            #pragma unroll
            for (int bb = 0; bb < 8; bb++) acc[bb] += hh[bb][j] * w;
        }
        float bi = b_I[tid];
        #pragma unroll
        for (int bb = 0; bb < 8; bb++) cps[bb][tid] = acc[bb] + bi;
    }
    __syncthreads();

    {   // u[b,o] = W_oI[o,:] . cps[b,:] + b_oI[o]   (o = tid)
        float acc[8];
        #pragma unroll
        for (int bb = 0; bb < 8; bb++) acc[bb] = 0.f;
        const float* wr = W_oI + tid * H;
        for (int i = 0; i < H; i++) {
            float w = wr[i];
            #pragma unroll
            for (int bb = 0; bb < 8; bb++) acc[bb] += cps[bb][i] * w;
        }
        float bo = b_oI[tid];
        #pragma unroll
        for (int bb = 0; bb < 8; bb++) gU[(b0 + bb) * H + tid] = acc[bb] + bo;
    }
}

// ---------------- k_main: fused GEMM + tanh + v-dot -> scores ---------------
// Y = H_hist[BT,H] @ M^T ; score[r] = sum_c v[c]*tanh(Y + u_b + dT*gT + dL*gL)
// Tile: 64 rows x 256 cols, BK=16, 256 threads, 8 rows x 4 col-pairs / thread.
// Software-pipelined: global loads for slab k0+1 issued before computing k0.
__global__ void __launch_bounds__(256, 2)
k_main(const float* __restrict__ h_hist,
       const float* __restrict__ dT,
       const float* __restrict__ dL,
       const float* __restrict__ v_t) {
    __shared__ float As[64 * 16];     //  4 KB
    __shared__ float Bs[16 * 256];    // 16 KB  Bs[k][c] = M[c][k0+k]

    const int tid = threadIdx.x;
    const int tx  = tid & 31;
    const int ty  = tid >> 5;
    const int r0  = blockIdx.x * 64;  // 64 | 256 -> whole tile in one batch
    const int b   = r0 >> 8;

    unsigned long long acc[8][4];
    #pragma unroll
    for (int i = 0; i < 8; i++)
        #pragma unroll
        for (int j = 0; j < 4; j++) acc[i][j] = 0ull;

    const int arow = tid >> 2;
    const int akk  = (tid & 3) * 4;
    const float* aptr = h_hist + (size_t)(r0 + arow) * H + akk;
    const float4* mrow = reinterpret_cast<const float4*>(gM + tid * H);

    // prefetch slab 0
    float4 av = *reinterpret_cast<const float4*>(aptr);
    float4 m0 = mrow[0], m1 = mrow[1], m2 = mrow[2], m3 = mrow[3];

    for (int k0 = 0; k0 < H; k0 += 16) {
        // commit prefetched slab to smem
        *reinterpret_cast<float4*>(As + arow * 16 + akk) = av;
        Bs[ 0 * 256 + tid] = m0.x;  Bs[ 1 * 256 + tid] = m0.y;
        Bs[ 2 * 256 + tid] = m0.z;  Bs[ 3 * 256 + tid] = m0.w;
        Bs[ 4 * 256 + tid] = m1.x;  Bs[ 5 * 256 + tid] = m1.y;
        Bs[ 6 * 256 + tid] = m1.z;  Bs[ 7 * 256 + tid] = m1.w;
        Bs[ 8 * 256 + tid] = m2.x;  Bs[ 9 * 256 + tid] = m2.y;
        Bs[10 * 256 + tid] = m2.z;  Bs[11 * 256 + tid] = m2.w;
        Bs[12 * 256 + tid] = m3.x;  Bs[13 * 256 + tid] = m3.y;
        Bs[14 * 256 + tid] = m3.z;  Bs[15 * 256 + tid] = m3.w;
        __syncthreads();

        // prefetch next slab while computing this one
        if (k0 + 16 < H) {
            const float* ap = aptr + k0 + 16;
            av = *reinterpret_cast<const float4*>(ap);
            const float4* mp = mrow + (k0 + 16) / 4;
            m0 = mp[0]; m1 = mp[1]; m2 = mp[2]; m3 = mp[3];
        }

        #pragma unroll
        for (int k = 0; k < 16; k++) {
            unsigned long long bb[4];
            #pragma unroll
            for (int j = 0; j < 4; j++)   // LDS.64, lane stride 8B: no conflicts
                bb[j] = *reinterpret_cast<const unsigned long long*>(
                    Bs + k * 256 + tx * 2 + 64 * j);
            #pragma unroll
            for (int i = 0; i < 8; i++) {
                float a = As[(ty * 8 + i) * 16 + k];   // warp broadcast
                unsigned long long aa = pack2(a, a);
                #pragma unroll
                for (int j = 0; j < 4; j++) ffma2(acc[i][j], aa, bb[j]);
            }
        }
        __syncthreads();
    }

    // epilogue: P = Y + u_b + dT*gT + dL*gL ; score = sum v*tanh(P)
    float2 u2[4], t2[4], l2[4], v2[4];
    #pragma unroll
    for (int j = 0; j < 4; j++) {
        int c = tx * 2 + 64 * j;
        u2[j] = *reinterpret_cast<const float2*>(gU + b * H + c);
        t2[j] = *reinterpret_cast<const float2*>(gGT + c);
        l2[j] = *reinterpret_cast<const float2*>(gGL + c);
        v2[j] = *reinterpret_cast<const float2*>(v_t + c);
    }
    #pragma unroll
    for (int i = 0; i < 8; i++) {
        int r = r0 + ty * 8 + i;
        float dt = dT[r];
        float dl = dL[r];
        float s = 0.f;
        #pragma unroll
        for (int j = 0; j < 4; j++) {
            float2 a = unpack2(acc[i][j]);
            float p0 = a.x + u2[j].x + dt * t2[j].x + dl * l2[j].x;
            float p1 = a.y + u2[j].y + dt * t2[j].y + dl * l2[j].y;
            s += v2[j].x * tanhf(p0) + v2[j].y * tanhf(p1);
        }
        #pragma unroll
        for (int off = 16; off; off >>= 1)
            s += __shfl_xor_sync(0xffffffffu, s, off);
        if (tx == 0) gScores[r] = s;
    }
}

// ---------------- k_alpha_st: softmax over T + s_t = alpha @ h_history ------
// One block per batch, 256 threads. Softmax result kept in smem, feeds s_t.
__global__ void k_alpha_st(const float* __restrict__ h_hist,
                           float* __restrict__ out_a,
                           float* __restrict__ out_s) {
    __shared__ float al[T];
    __shared__ float redm[8];
    __shared__ float reds[8];
    __shared__ float bcast[2];
    int b = blockIdx.x, t = threadIdx.x;
    int lane = t & 31, w = t >> 5;

    float s = gScores[b * T + t];

    float m = s;
    #pragma unroll
    for (int off = 16; off; off >>= 1)
        m = fmaxf(m, __shfl_xor_sync(0xffffffffu, m, off));
    if (lane == 0) redm[w] = m;
    __syncthreads();
    if (t == 0) {
        float mm = redm[0];
        #pragma unroll
        for (int i = 1; i < 8; i++) mm = fmaxf(mm, redm[i]);
        bcast[0] = mm;
    }
    __syncthreads();
    float e = __expf(s - bcast[0]);

    float su = e;
    #pragma unroll
    for (int off = 16; off; off >>= 1)
        su += __shfl_xor_sync(0xffffffffu, su, off);
    if (lane == 0) reds[w] = su;
    __syncthreads();
    if (t == 0) {
        float ss = 0.f;
        #pragma unroll
        for (int i = 0; i < 8; i++) ss += reds[i];
        bcast[1] = 1.f / ss;
    }
    __syncthreads();

    float a = e * bcast[1];
    al[t] = a;
    out_a[b * T + t] = a;
    __syncthreads();

    // s_t[b, h=t] = sum_t2 alpha[t2] * h_hist[b, t2, h]
    float acc = 0.f;
    const float* hp = h_hist + (size_t)b * T * H + t;
    #pragma unroll 8
    for (int t2 = 0; t2 < T; t2++) acc += al[t2] * hp[t2 * H];
    out_s[b * H + t] = acc;
}

// ---------------- launch ----------------------------------------------------
extern "C" void kernel_launch(void* const* d_in, const int* in_sizes, int n_in,
                              void* d_out, int out_size) {
    const float* h_tilde = (const float*)d_in[0];
    const float* c_t     = (const float*)d_in[1];
    const float* h_hist  = (const float*)d_in[2];
    const float* dT      = (const float*)d_in[3];
    const float* dL      = (const float*)d_in[4];
    const float* W_I     = (const float*)d_in[5];
    const float* W_Ih    = (const float*)d_in[6];
    const float* wT      = (const float*)d_in[7];
    const float* wL      = (const float*)d_in[8];
    const float* b_I     = (const float*)d_in[9];
    const float* W_oI    = (const float*)d_in[10];
    const float* b_oI    = (const float*)d_in[11];
    const float* v_t     = (const float*)d_in[12];

    float* out   = (float*)d_out;
    float* out_s = out;           // s_t  [B,H]
    float* out_a = out + B * H;   // alpha[B,T]

    k_vec<<<1, 256>>>(W_oI, wT, wL);
    k_M<<<H / 4, 256>>>(W_oI, W_Ih);
    k_u<<<B / 8, 256>>>(h_tilde, c_t, W_I, W_oI, b_I, b_oI);
    k_main<<<BT / 64, 256>>>(h_hist, dT, dL, v_t);
    k_alpha_st<<<B, 256>>>(h_hist, out_a, out_s);
}

// round 7
// speedup vs baseline: 2.0122x; 2.0122x over previous
#include <cuda_runtime.h>
#include <cuda_bf16.h>
#include <math.h>
#include <stdint.h>

#define H  256
#define B  512
#define T  256
#define BT (B*T)

// ================= device scratch (no allocations allowed) ==================
__device__ float gM[H * H];            // M = W_oI @ W_Ih  (row n, col k), fp32
__device__ float gGT[H];               // W_oI @ W_I1T
__device__ float gGL[H];               // W_oI @ W_I1L
__device__ float gU[B * H];            // u_b = W_oI @ (cp_b + b_I) + b_oI
__device__ float gScores[BT];          // pre-softmax scores
// B fragments in mma register layout, lane-major for coalesced LDG.128:
// uint4 index = ((kt*2 + reg)*8 + g8)*32 + lane ; the 4 words are 4 n-tiles.
__device__ uint4 gBhi[16 * 2 * 8 * 32];   // 128 KB
__device__ uint4 gBlo[16 * 2 * 8 * 32];   // 128 KB

// ===================== helpers ====================================
__device__ __forceinline__ float tanh_fast(float x) {
    float ax = fabsf(x);
    float t  = __expf(-2.0f * ax);              // (0,1], no overflow
    float r  = __fdividef(1.0f - t, 1.0f + t);
    return copysignf(r, x);
}
__device__ __forceinline__ uint32_t pack_bf16x2(float lo_elem, float hi_elem) {
    __nv_bfloat162 p = __floats2bfloat162_rn(lo_elem, hi_elem); // .x = low half
    return *reinterpret_cast<uint32_t*>(&p);
}

// d += A(16x16 bf16) @ B(16x8 bf16), f32 accumulate. Plain PTX, sm_80+.
#define MMA16816(d, a0, a1, a2, a3, b0, b1)                                   \
    asm volatile("mma.sync.aligned.m16n8k16.row.col.f32.bf16.bf16.f32 "       \
        "{%0,%1,%2,%3}, {%4,%5,%6,%7}, {%8,%9}, {%0,%1,%2,%3};"               \
        : "+f"((d)[0]), "+f"((d)[1]), "+f"((d)[2]), "+f"((d)[3])              \
        : "r"(a0), "r"(a1), "r"(a2), "r"(a3), "r"(b0), "r"(b1))

// ================= k_vec: gGT = W_oI@wT, gGL = W_oI@wL ======================
__global__ void k_vec(const float* __restrict__ W_oI,
                      const float* __restrict__ wT,
                      const float* __restrict__ wL) {
    int o = threadIdx.x;
    float at = 0.f, al = 0.f;
    const float* wr = W_oI + o * H;
    for (int i = 0; i < H; i++) {
        float w = wr[i];
        at += w * wT[i];
        al += w * wL[i];
    }
    gGT[o] = at;
    gGL[o] = al;
}

// ========== k_M: M = W_oI @ W_Ih (fp32) =====================================
__global__ void k_M(const float* __restrict__ W_oI,
                    const float* __restrict__ W_Ih) {
    __shared__ float sWo[4][H];
    int h  = threadIdx.x;
    int o0 = blockIdx.x * 4;
    #pragma unroll
    for (int r = 0; r < 4; r++) sWo[r][h] = W_oI[(o0 + r) * H + h];
    __syncthreads();
    float a[4] = {0.f, 0.f, 0.f, 0.f};
    for (int i = 0; i < H; i++) {
        float w = W_Ih[i * H + h];              // coalesced
        a[0] += sWo[0][i] * w;
        a[1] += sWo[1][i] * w;
        a[2] += sWo[2][i] * w;
        a[3] += sWo[3][i] * w;
    }
    #pragma unroll
    for (int r = 0; r < 4; r++) gM[(o0 + r) * H + h] = a[r];
}

// ========== k_frag: pack gM into mma B-fragment layout (hi/lo bf16) =========
// 256 blocks x 128 threads. block = (kt, reg, g8); thread = lane*4 + j.
// B[k][n] = M[n][k];  b_reg r: k = kt*16 + r*8 + 2*(lane&3) + {0,1},
//                     n = ntile*8 + (lane>>2),  ntile = g8*4 + j.
__global__ void k_frag() {
    int bid  = blockIdx.x;
    int kt   = bid >> 4;
    int reg  = (bid >> 3) & 1;
    int g8   = bid & 7;
    int tid  = threadIdx.x;
    int lane = tid >> 2;
    int j    = tid & 3;

    int ntg = g8 * 4 + j;
    int n   = ntg * 8 + (lane >> 2);
    int k   = kt * 16 + reg * 8 + 2 * (lane & 3);

    float m0 = gM[n * H + k];
    float m1 = gM[n * H + k + 1];
    float h0 = __bfloat162float(__float2bfloat16(m0));
    float h1 = __bfloat162float(__float2bfloat16(m1));

    uint32_t* outh = reinterpret_cast<uint32_t*>(gBhi);
    uint32_t* outl = reinterpret_cast<uint32_t*>(gBlo);
    outh[bid * 128 + tid] = pack_bf16x2(m0, m1);          // rn(m) = hi
    outl[bid * 128 + tid] = pack_bf16x2(m0 - h0, m1 - h1);
}

// ========== k_u: gU, coalesced smem-tiled (64 blocks x 8 batches) ===========
__global__ void k_u(const float* __restrict__ h_tilde,
                    const float* __restrict__ c_t,
                    const float* __restrict__ W_I,
                    const float* __restrict__ W_oI,
                    const float* __restrict__ b_I,
                    const float* __restrict__ b_oI) {
    __shared__ float hh[8][2 * H];    // 16 KB
    __shared__ float cps[8][H];       //  8 KB
    __shared__ float wt[256][17];     // ~17 KB, padded
    int tid = threadIdx.x;
    int b0  = blockIdx.x * 8;

    for (int idx = tid; idx < 8 * 2 * H; idx += 256) {
        int bb = idx >> 9, j = idx & (2 * H - 1);
        hh[bb][j] = (j < H) ? h_tilde[(b0 + bb) * H + j]
                            : c_t[(b0 + bb) * H + (j - H)];
    }

    float acc[8];
    #pragma unroll
    for (int bb = 0; bb < 8; bb++) acc[bb] = 0.f;
    for (int jt = 0; jt < 32; jt++) {
        __syncthreads();
        #pragma unroll
        for (int q = 0; q < 4; q++) {
            int idx = q * 256 + tid;
            int row = idx >> 2, c4 = idx & 3;
            float4 w = *reinterpret_cast<const float4*>(
                W_I + row * (2 * H) + jt * 16 + c4 * 4);
            wt[row][c4 * 4 + 0] = w.x;  wt[row][c4 * 4 + 1] = w.y;
            wt[row][c4 * 4 + 2] = w.z;  wt[row][c4 * 4 + 3] = w.w;
        }
        __syncthreads();
        #pragma unroll
        for (int j = 0; j < 16; j++) {
            float w = wt[tid][j];
            #pragma unroll
            for (int bb = 0; bb < 8; bb++) acc[bb] += hh[bb][jt * 16 + j] * w;
        }
    }
    {
        float bi = b_I[tid];
        #pragma unroll
        for (int bb = 0; bb < 8; bb++) cps[bb][tid] = acc[bb] + bi;
    }

    float acc2[8];
    #pragma unroll
    for (int bb = 0; bb < 8; bb++) acc2[bb] = 0.f;
    for (int it = 0; it < 16; it++) {
        __syncthreads();
        #pragma unroll
        for (int q = 0; q < 4; q++) {
            int idx = q * 256 + tid;
            int row = idx >> 2, c4 = idx & 3;
            float4 w = *reinterpret_cast<const float4*>(
                W_oI + row * H + it * 16 + c4 * 4);
            wt[row][c4 * 4 + 0] = w.x;  wt[row][c4 * 4 + 1] = w.y;
            wt[row][c4 * 4 + 2] = w.z;  wt[row][c4 * 4 + 3] = w.w;
        }
        __syncthreads();
        #pragma unroll
        for (int j = 0; j < 16; j++) {
            float w = wt[tid][j];
            #pragma unroll
            for (int bb = 0; bb < 8; bb++) acc2[bb] += cps[bb][it * 16 + j] * w;
        }
    }
    float bo = b_oI[tid];
    #pragma unroll
    for (int bb = 0; bb < 8; bb++) gU[(b0 + bb) * H + tid] = acc2[bb] + bo;
}

// ========== k_main_mma: bf16x3 mma.sync GEMM + fused tanh/v-dot =============
// CTA: 64 rows x 256 cols, 8 warps = 4 row-groups x 2 N-halves.
// Warp: m16 x n128 (16 n-tiles), K=256 in 16 k-tiles of 16.
#define AROW 264                      // bf16 per smem A row (256 + 8 pad)
#define SM_AHI 0                      // 64 x 528B = 33792
#define SM_ALO 33792                  // 33792
#define SM_CU  67584                  // u|gT|gL|v : 4*256 f32 = 4096
#define SM_SC  71680                  // 64 x 2 f32 = 512
#define SMEM_TOTAL 72192

__global__ void __launch_bounds__(256, 2)
k_main_mma(const float* __restrict__ h_hist,
           const float* __restrict__ dT,
           const float* __restrict__ dL,
           const float* __restrict__ v_t) {
    extern __shared__ char smem[];
    __nv_bfloat16* Ahi = reinterpret_cast<__nv_bfloat16*>(smem + SM_AHI);
    __nv_bfloat16* Alo = reinterpret_cast<__nv_bfloat16*>(smem + SM_ALO);
    float* cu = reinterpret_cast<float*>(smem + SM_CU);
    float* sc = reinterpret_cast<float*>(smem + SM_SC);

    const int tid  = threadIdx.x;
    const int wid  = tid >> 5;
    const int lane = tid & 31;
    const int r0   = blockIdx.x * 64;     // 64 | 256 -> single batch per CTA
    const int b    = r0 >> 8;

    // constants to smem
    cu[tid]       = gU[b * H + tid];
    cu[256 + tid] = gGT[tid];
    cu[512 + tid] = gGL[tid];
    cu[768 + tid] = v_t[tid];

    // ---- stage A tile (64x256 fp32 -> bf16 hi/lo), coalesced float4 ----
    #pragma unroll
    for (int i = 0; i < 16; i++) {
        int f   = i * 256 + tid;          // float4 index over 64x64
        int row = f >> 6;
        int c4  = f & 63;
        float4 a = *reinterpret_cast<const float4*>(
            h_hist + (size_t)(r0 + row) * H + c4 * 4);
        float hx = __bfloat162float(__float2bfloat16(a.x));
        float hy = __bfloat162float(__float2bfloat16(a.y));
        float hz = __bfloat162float(__float2bfloat16(a.z));
        float hw = __bfloat162float(__float2bfloat16(a.w));
        uint32_t* ph = reinterpret_cast<uint32_t*>(Ahi + row * AROW + c4 * 4);
        uint32_t* pl = reinterpret_cast<uint32_t*>(Alo + row * AROW + c4 * 4);
        ph[0] = pack_bf16x2(a.x, a.y);
        ph[1] = pack_bf16x2(a.z, a.w);
        pl[0] = pack_bf16x2(a.x - hx, a.y - hy);
        pl[1] = pack_bf16x2(a.z - hz, a.w - hw);
    }
    __syncthreads();

    const int rg = wid >> 1;              // row group 0..3
    const int nh = wid & 1;               // N half 0..1
    const int ar = rg * 16 + (lane >> 2); // A fragment row (low)

    float acc[16][4];
    #pragma unroll
    for (int i = 0; i < 16; i++)
        #pragma unroll
        for (int j = 0; j < 4; j++) acc[i][j] = 0.f;

    #pragma unroll 4
    for (int kt = 0; kt < 16; kt++) {
        const int kc = kt * 16 + 2 * (lane & 3);
        // A fragments (conflict-free: 528B row stride = 4-bank shift/row)
        uint32_t ah0 = *reinterpret_cast<uint32_t*>(Ahi + ar * AROW + kc);
        uint32_t ah1 = *reinterpret_cast<uint32_t*>(Ahi + (ar + 8) * AROW + kc);
        uint32_t ah2 = *reinterpret_cast<uint32_t*>(Ahi + ar * AROW + kc + 8);
        uint32_t ah3 = *reinterpret_cast<uint32_t*>(Ahi + (ar + 8) * AROW + kc + 8);
        uint32_t al0 = *reinterpret_cast<uint32_t*>(Alo + ar * AROW + kc);
        uint32_t al1 = *reinterpret_cast<uint32_t*>(Alo + (ar + 8) * AROW + kc);
        uint32_t al2 = *reinterpret_cast<uint32_t*>(Alo + ar * AROW + kc + 8);
        uint32_t al3 = *reinterpret_cast<uint32_t*>(Alo + (ar + 8) * AROW + kc + 8);

        #pragma unroll
        for (int g = 0; g < 4; g++) {
            const int g8 = nh * 4 + g;
            uint4 bh0 = gBhi[((kt * 2 + 0) * 8 + g8) * 32 + lane];
            uint4 bh1 = gBhi[((kt * 2 + 1) * 8 + g8) * 32 + lane];
            uint4 bl0 = gBlo[((kt * 2 + 0) * 8 + g8) * 32 + lane];
            uint4 bl1 = gBlo[((kt * 2 + 1) * 8 + g8) * 32 + lane];
            const uint32_t* h0 = reinterpret_cast<const uint32_t*>(&bh0);
            const uint32_t* h1 = reinterpret_cast<const uint32_t*>(&bh1);
            const uint32_t* l0 = reinterpret_cast<const uint32_t*>(&bl0);
            const uint32_t* l1 = reinterpret_cast<const uint32_t*>(&bl1);
            #pragma unroll
            for (int j = 0; j < 4; j++) {
                float* d = acc[g * 4 + j];
                MMA16816(d, ah0, ah1, ah2, ah3, h0[j], h1[j]);  // hi*hi
                MMA16816(d, ah0, ah1, ah2, ah3, l0[j], l1[j]);  // hi*lo
                MMA16816(d, al0, al1, al2, al3, h0[j], h1[j]);  // lo*hi
            }
        }
    }

    // ---- epilogue: tanh + v-dot, reduce over lane%4 then N halves ----
    const float dt0 = dT[r0 + ar],     dl0 = dL[r0 + ar];
    const float dt1 = dT[r0 + ar + 8], dl1 = dL[r0 + ar + 8];
    float s0 = 0.f, s1 = 0.f;
    #pragma unroll
    for (int nt = 0; nt < 16; nt++) {
        const int c = (nh * 16 + nt) * 8 + 2 * (lane & 3);
        float u0 = cu[c],       u1 = cu[c + 1];
        float t0 = cu[256 + c], t1 = cu[256 + c + 1];
        float l0 = cu[512 + c], l1 = cu[512 + c + 1];
        float v0 = cu[768 + c], v1 = cu[768 + c + 1];
        s0 += v0 * tanh_fast(acc[nt][0] + u0 + dt0 * t0 + dl0 * l0);
        s0 += v1 * tanh_fast(acc[nt][1] + u1 + dt0 * t1 + dl0 * l1);
        s1 += v0 * tanh_fast(acc[nt][2] + u0 + dt1 * t0 + dl1 * l0);
        s1 += v1 * tanh_fast(acc[nt][3] + u1 + dt1 * t1 + dl1 * l1);
    }
    s0 += __shfl_xor_sync(0xffffffffu, s0, 1);
    s0 += __shfl_xor_sync(0xffffffffu, s0, 2);
    s1 += __shfl_xor_sync(0xffffffffu, s1, 1);
    s1 += __shfl_xor_sync(0xffffffffu, s1, 2);
    if ((lane & 3) == 0) {
        sc[ar * 2 + nh]       = s0;
        sc[(ar + 8) * 2 + nh] = s1;
    }
    __syncthreads();
    if (tid < 64) gScores[r0 + tid] = sc[tid * 2] + sc[tid * 2 + 1];
}

// ========== k_alpha_st: softmax over T + s_t = alpha @ h_history ============
__global__ void k_alpha_st(const float* __restrict__ h_hist,
                           float* __restrict__ out_a,
                           float* __restrict__ out_s) {
    __shared__ float al[T];
    __shared__ float redm[8];
    __shared__ float reds[8];
    __shared__ float bcast[2];
    int b = blockIdx.x, t = threadIdx.x;
    int lane = t & 31, w = t >> 5;

    float s = gScores[b * T + t];

    float m = s;
    #pragma unroll
    for (int off = 16; off; off >>= 1)
        m = fmaxf(m, __shfl_xor_sync(0xffffffffu, m, off));
    if (lane == 0) redm[w] = m;
    __syncthreads();
    if (t == 0) {
        float mm = redm[0];
        #pragma unroll
        for (int i = 1; i < 8; i++) mm = fmaxf(mm, redm[i]);
        bcast[0] = mm;
    }
    __syncthreads();
    float e = __expf(s - bcast[0]);

    float su = e;
    #pragma unroll
    for (int off = 16; off; off >>= 1)
        su += __shfl_xor_sync(0xffffffffu, su, off);
    if (lane == 0) reds[w] = su;
    __syncthreads();
    if (t == 0) {
        float ss = 0.f;
        #pragma unroll
        for (int i = 0; i < 8; i++) ss += reds[i];
        bcast[1] = 1.f / ss;
    }
    __syncthreads();

    float a = e * bcast[1];
    al[t] = a;
    out_a[b * T + t] = a;
    __syncthreads();

    float acc = 0.f;
    const float* hp = h_hist + (size_t)b * T * H + t;
    #pragma unroll 8
    for (int t2 = 0; t2 < T; t2++) acc += al[t2] * hp[t2 * H];
    out_s[b * H + t] = acc;
}

// =========================== launch ========================================
extern "C" void kernel_launch(void* const* d_in, const int* in_sizes, int n_in,
                              void* d_out, int out_size) {
    const float* h_tilde = (const float*)d_in[0];
    const float* c_t     = (const float*)d_in[1];
    const float* h_hist  = (const float*)d_in[2];
    const float* dT      = (const float*)d_in[3];
    const float* dL      = (const float*)d_in[4];
    const float* W_I     = (const float*)d_in[5];
    const float* W_Ih    = (const float*)d_in[6];
    const float* wT      = (const float*)d_in[7];
    const float* wL      = (const float*)d_in[8];
    const float* b_I     = (const float*)d_in[9];
    const float* W_oI    = (const float*)d_in[10];
    const float* b_oI    = (const float*)d_in[11];
    const float* v_t     = (const float*)d_in[12];

    float* out   = (float*)d_out;
    float* out_s = out;            // s_t   [B,H]
    float* out_a = out + B * H;    // alpha [B,T]

    // Unconditional (idempotent; no static guards allowed).
    cudaFuncSetAttribute(k_main_mma,
                         cudaFuncAttributeMaxDynamicSharedMemorySize,
                         SMEM_TOTAL);

    k_vec<<<1, 256>>>(W_oI, wT, wL);
    k_M<<<H / 4, 256>>>(W_oI, W_Ih);
    k_frag<<<256, 128>>>();
    k_u<<<B / 8, 256>>>(h_tilde, c_t, W_I, W_oI, b_I, b_oI);
    k_main_mma<<<BT / 64, 256, SMEM_TOTAL>>>(h_hist, dT, dL, v_t);
    k_alpha_st<<<B, 256>>>(h_hist, out_a, out_s);
}